// round 15
// baseline (speedup 1.0000x reference)
#include <cuda_runtime.h>
#include <cuda_fp16.h>
#include <math.h>
#include <stdint.h>

// ---------------------------------------------------------------------------
// Mamba block: B=4, L=2048, dim=1024, d_inner=2048, d_state=16, K=4, dt_rank=64
// Baseline sm_103 PTX -> ldmatrix + mma.sync fp16 HMMA (fp32 accum).
// System is effective-BW bound (~2 TB/s): optimize by CUTTING BYTES.
// R15 = R13 winner (128x128 GEMM tiles, >=2 CTAs/SM — 1 CTA/SM pinned bad
// twice) + dbc-path byte cuts: KSPLIT=2, 96-col partials, dead-write removal.
// ---------------------------------------------------------------------------
#define BB      4
#define LL      2048
#define DIM     1024
#define DINNER  2048
#define DSTATE  16
#define DCONV   4
#define DTRANK  64
#define NTOK    (BB * LL)              // 8192
#define DBC_W   (DTRANK + 2 * DSTATE)  // 96
#define KSPLIT  2
#define NSEG    8
#define SEGLEN  (LL / NSEG)            // 256

// ---------------------------------------------------------------------------
// Scratch (device globals; zero-initialized)
// ---------------------------------------------------------------------------
__device__ __half g_xz[(size_t)NTOK * 2 * DINNER];       // z half stores silu(z)
__device__ float  g_dbc[(size_t)NTOK * DBC_W];
__device__ float  g_dbcp[(size_t)KSPLIT * NTOK * 128];
__device__ __half g_delta[(size_t)NTOK * DINNER];
__device__ __half g_xn[(size_t)NTOK * DIM];
__device__ __half g_xi[(size_t)NTOK * DINNER];
__device__ __half g_dt[(size_t)NTOK * DTRANK];
__device__ __half g_g[(size_t)NTOK * DINNER];
__device__ float  g_segsum[(size_t)NSEG * BB * DINNER];
__device__ float  g_segc[(size_t)NSEG * BB * DINNER * DSTATE];
__device__ __half g_ipT[(size_t)(2 * DINNER) * DIM];
__device__ __half g_xpT[(size_t)128 * DINNER];
__device__ __half g_dwT[(size_t)DINNER * DTRANK];
__device__ __half g_opT[(size_t)DIM * DINNER];

// ---------------------------------------------------------------------------
// PTX helpers
// ---------------------------------------------------------------------------
__device__ __forceinline__ uint32_t smem_u32(const void* p) {
    uint32_t a;
    asm("{ .reg .u64 t; cvta.to.shared.u64 t, %1; cvt.u32.u64 %0, t; }" : "=r"(a) : "l"(p));
    return a;
}
__device__ __forceinline__ void cp16(uint32_t dst, const void* src) {
    asm volatile("cp.async.cg.shared.global [%0], [%1], 16;" :: "r"(dst), "l"(src));
}
#define CP_COMMIT() asm volatile("cp.async.commit_group;" ::: "memory")
#define CP_WAIT(n)  asm volatile("cp.async.wait_group %0;" :: "n"(n) : "memory")

#define LDSM4(r, a) \
    asm volatile("ldmatrix.sync.aligned.m8n8.x4.shared.b16 {%0,%1,%2,%3}, [%4];" \
        : "=r"((r)[0]), "=r"((r)[1]), "=r"((r)[2]), "=r"((r)[3]) : "r"(a))

#define MMA16816(d, a, b0, b1) \
    asm volatile("mma.sync.aligned.m16n8k16.row.col.f32.f16.f16.f32 " \
        "{%0,%1,%2,%3}, {%4,%5,%6,%7}, {%8,%9}, {%0,%1,%2,%3};" \
        : "+f"((d)[0]), "+f"((d)[1]), "+f"((d)[2]), "+f"((d)[3]) \
        : "r"((a)[0]), "r"((a)[1]), "r"((a)[2]), "r"((a)[3]), "r"(b0), "r"(b1))

__device__ __forceinline__ void exp_powers(float E, float* P) {
    float E2 = E * E, E4 = E2 * E2, E8 = E4 * E4;
    P[0]=E;      P[1]=E2;      P[2]=E2*E;     P[3]=E4;
    P[4]=E4*E;   P[5]=E4*E2;   P[6]=E4*P[2];  P[7]=E8;
    P[8]=E8*E;   P[9]=E8*E2;   P[10]=E8*P[2]; P[11]=E8*E4;
    P[12]=E8*P[4]; P[13]=E8*P[5]; P[14]=E8*P[6]; P[15]=E8*E8;
}

// ---------------------------------------------------------------------------
// Fused prep: weight transposes + rmsnorm, one grid.
// ---------------------------------------------------------------------------
__device__ __forceinline__ void transpose_tile(const float* __restrict__ W,
                                               __half* __restrict__ T,
                                               int R, int C, int cb, int rb) {
    __shared__ float t[32][33];
    const int tx = threadIdx.x & 31, ty = threadIdx.x >> 5;
    int c0 = cb * 32, r0 = rb * 32;
    int c = c0 + tx;
    for (int i = ty; i < 32; i += 8) {
        int r = r0 + i;
        if (r < R && c < C) t[i][tx] = W[(size_t)r * C + c];
    }
    __syncthreads();
    int k = r0 + tx;
    for (int i = ty; i < 32; i += 8) {
        int n = c0 + i;
        if (n < C && k < R)
            T[(size_t)n * R + k] = __float2half(t[tx][i]);
    }
}

__global__ void __launch_bounds__(256)
prep_kernel(const float* __restrict__ in_proj, const float* __restrict__ x_proj,
            const float* __restrict__ dt_w,    const float* __restrict__ out_proj,
            __half* __restrict__ ipT, __half* __restrict__ xpT,
            __half* __restrict__ dwT, __half* __restrict__ opT,
            const float* __restrict__ x, const float* __restrict__ rms_w,
            __half* __restrict__ xn) {
    int bid = blockIdx.x;
    if (bid < 4096) {
        transpose_tile(in_proj, ipT, DIM, 2 * DINNER, bid & 127, bid >> 7);
    } else if (bid < 4288) {
        int i = bid - 4096;
        transpose_tile(x_proj, xpT, DINNER, DBC_W, i % 3, i / 3);
    } else if (bid < 4416) {
        int i = bid - 4288;
        transpose_tile(dt_w, dwT, DTRANK, DINNER, i & 63, i >> 6);
    } else if (bid < 6464) {
        int i = bid - 4416;
        transpose_tile(out_proj, opT, DINNER, DIM, i & 31, i >> 5);
    } else {
        int t = bid - 6464;
        const float* xr = x + (size_t)t * DIM;
        float s = 0.f;
        for (int i = threadIdx.x; i < DIM; i += 256) { float v = xr[i]; s += v * v; }
        #pragma unroll
        for (int off = 16; off > 0; off >>= 1) s += __shfl_xor_sync(0xffffffffu, s, off);
        __shared__ float red[8];
        int wid = threadIdx.x >> 5;
        if ((threadIdx.x & 31) == 0) red[wid] = s;
        __syncthreads();
        __shared__ float sscale;
        if (threadIdx.x == 0) {
            float tot = 0.f;
            #pragma unroll
            for (int i = 0; i < 8; i++) tot += red[i];
            sscale = rsqrtf(tot * (1.0f / DIM) + 1e-5f);
        }
        __syncthreads();
        float scale = sscale;
        for (int i = threadIdx.x * 2; i < DIM; i += 512) {
            float2 v = *(const float2*)(xr + i);
            float2 wv = *(const float2*)(rms_w + i);
            *(__half2*)(xn + (size_t)t * DIM + i) =
                __floats2half2_rn(v.x * scale * wv.x, v.y * scale * wv.y);
        }
    }
}

// ---------------------------------------------------------------------------
// mma.sync fp16 GEMM (128x128, 256 thr, 4-stage cp.async, 2 CTAs/SM).
// MODE 1: softplus(+bias) -> fp16  2: +res -> fp32
// MODE 4: fp16 out, silu applied to columns >= DINNER (the z half)
// ---------------------------------------------------------------------------
#define TSB   10240
#define STGB  (2 * TSB)
#define SMEM_GEMM (4 * STGB)          // 81920

template<int MODE>
__global__ void __launch_bounds__(256)
mma_gemm(const __half* __restrict__ A, const __half* __restrict__ B,
         void* __restrict__ Cv, int N, int K, int ld,
         const float* __restrict__ extra) {
    extern __shared__ char smem[];
    const uint32_t sb = smem_u32(smem);
    const int tid  = threadIdx.x;
    const int lane = tid & 31;
    const int wid  = tid >> 5;
    const int wm = (wid & 3) * 32;
    const int wn = (wid >> 2) * 64;
    const int row0 = blockIdx.y * 128;
    const int col0 = blockIdx.x * 128;
    const int nch = K >> 5;

    float*  Cf = (float*)Cv;
    __half* Ch = (__half*)Cv;

    auto load_stage = [&](int st, int k0) {
        uint32_t base = sb + st * STGB;
        #pragma unroll
        for (int u = 0; u < 2; u++) {
            int i = u * 256 + tid;
            int r = i >> 2, seg = i & 3;
            uint32_t d = base + r * 80 + seg * 16;
            cp16(d,       A + (size_t)(row0 + r) * ld + k0 + seg * 8);
            cp16(d + TSB, B + (size_t)(col0 + r) * ld + k0 + seg * 8);
        }
    };

    float acc[2][8][4];
    #pragma unroll
    for (int mi = 0; mi < 2; mi++)
        #pragma unroll
        for (int ni = 0; ni < 8; ni++)
            #pragma unroll
            for (int q = 0; q < 4; q++) acc[mi][ni][q] = 0.f;

    const int lrow = lane & 15;
    const int lkb  = lane >> 4;

    load_stage(0, 0);                      CP_COMMIT();
    if (nch > 1) load_stage(1, 32);        CP_COMMIT();
    if (nch > 2) load_stage(2, 64);        CP_COMMIT();

    for (int kc = 0; kc < nch; kc++) {
        CP_WAIT(2);
        __syncthreads();
        if (kc + 3 < nch) load_stage((kc + 3) & 3, (kc + 3) << 5);
        CP_COMMIT();

        uint32_t base = sb + (kc & 3) * STGB;
        #pragma unroll
        for (int ks = 0; ks < 2; ks++) {
            uint32_t koff = (ks * 16 + lkb * 8) * 2;
            uint32_t ah[2][4];
            #pragma unroll
            for (int mi = 0; mi < 2; mi++)
                LDSM4(ah[mi], base + (wm + mi * 16 + lrow) * 80 + koff);
            uint32_t bf[4][4];
            #pragma unroll
            for (int p = 0; p < 4; p++)
                LDSM4(bf[p], base + TSB + (wn + p * 16 + lrow) * 80 + koff);
            #pragma unroll
            for (int mi = 0; mi < 2; mi++)
                #pragma unroll
                for (int p = 0; p < 4; p++)
                    #pragma unroll
                    for (int hb = 0; hb < 2; hb++)
                        MMA16816(acc[mi][p * 2 + hb], ah[mi], bf[p][hb], bf[p][hb + 2]);
        }
        __syncthreads();
    }

    const int rb = row0 + wm + (lane >> 2);
    const int cb = col0 + wn + (lane & 3) * 2;
    #pragma unroll
    for (int mi = 0; mi < 2; mi++)
        #pragma unroll
        for (int ni = 0; ni < 8; ni++) {
            int c = cb + ni * 8;
            if (c >= N) continue;
            #pragma unroll
            for (int half = 0; half < 2; half++) {
                int r = rb + mi * 16 + half * 8;
                float v0 = acc[mi][ni][half * 2 + 0];
                float v1 = acc[mi][ni][half * 2 + 1];
                if (MODE == 1) {
                    v0 += extra[c];     v1 += extra[c + 1];
                    v0 = (v0 > 20.f) ? v0 : log1pf(__expf(v0));
                    v1 = (v1 > 20.f) ? v1 : log1pf(__expf(v1));
                } else if (MODE == 2) {
                    const float2 res = *(const float2*)(extra + (size_t)r * N + c);
                    v0 += res.x; v1 += res.y;
                } else if (MODE == 4) {
                    if (c >= DINNER) {   // z half -> store silu(z)
                        v0 = v0 / (1.f + __expf(-v0));
                        v1 = v1 / (1.f + __expf(-v1));
                    }
                }
                if (MODE == 2)
                    *(float2*)(Cf + (size_t)r * N + c) = make_float2(v0, v1);
                else
                    *(__half2*)(Ch + (size_t)r * N + c) = __floats2half2_rn(v0, v1);
            }
        }
}

// ---------------------------------------------------------------------------
// GEMM2 fused: dbc partials = conv_silu(xz_x) @ xpT^T, AND writes xi.
// grid (1, NTOK/128, KSPLIT=2): each z covers K=1024 channels.
// Partials: only cols < 96 stored (96..127 are zero-weight padding).
// ---------------------------------------------------------------------------
#define RAWA  8384                    // 131 rows x 64 B
#define RSTG  (RAWA + TSB)            // 18624 per stage
#define AMMA_OFF (4 * RSTG)           // 74496
#define SMEM_G2  (AMMA_OFF + TSB)     // 84736

__global__ void __launch_bounds__(256)
gemm2_fused(const __half* __restrict__ xz,
            const __half* __restrict__ xpT,
            const float* __restrict__ conv_w,
            const float* __restrict__ conv_b,
            __half* __restrict__ xi,
            float* __restrict__ dbcp) {
    extern __shared__ char smem[];
    const uint32_t sb = smem_u32(smem);
    const int tid  = threadIdx.x;
    const int lane = tid & 31;
    const int wid  = tid >> 5;
    const int wm = (wid & 3) * 32;
    const int wn = (wid >> 2) * 64;
    const int row0 = blockIdx.y * 128;
    const int cz   = blockIdx.z * (DINNER / KSPLIT);
    const bool first = (row0 & (LL - 1)) == 0;
    const int nch = (DINNER / KSPLIT) >> 5;           // 32

    float* Cf = dbcp + (size_t)blockIdx.z * NTOK * 128;

    auto load_stage = [&](int st, int k0) {
        uint32_t base = sb + st * RSTG;
        #pragma unroll
        for (int u0 = 0; u0 < 5; u0++) {
            int u = u0 * 256 + tid;
            if (u >= 1036) break;
            if (u < 524) {
                int r = u >> 2, seg = u & 3;
                uint32_t d = base + r * 64 + seg * 16;
                if (first && r < 3) {
                    *(uint4*)(smem + (d - sb)) = make_uint4(0, 0, 0, 0);
                } else {
                    cp16(d, xz + (size_t)(row0 - 3 + r) * (2 * DINNER) + cz + k0 + seg * 8);
                }
            } else {
                int v = u - 524;
                int r = v >> 2, seg = v & 3;
                cp16(base + RAWA + r * 80 + seg * 16,
                     xpT + (size_t)r * DINNER + cz + k0 + seg * 8);
            }
        }
    };

    float acc[2][8][4];
    #pragma unroll
    for (int mi = 0; mi < 2; mi++)
        #pragma unroll
        for (int ni = 0; ni < 8; ni++)
            #pragma unroll
            for (int q = 0; q < 4; q++) acc[mi][ni][q] = 0.f;

    const int lrow = lane & 15;
    const int lkb  = lane >> 4;
    const int cch  = tid & 31;
    const int cg   = tid >> 5;

    load_stage(0, 0);   CP_COMMIT();
    load_stage(1, 32);  CP_COMMIT();
    load_stage(2, 64);  CP_COMMIT();

    for (int kc = 0; kc < nch; kc++) {
        CP_WAIT(2);
        __syncthreads();
        if (kc + 3 < nch) load_stage((kc + 3) & 3, (kc + 3) << 5);
        CP_COMMIT();

        const int k0 = kc << 5;
        uint32_t rawb = sb + (kc & 3) * RSTG;

        {
            const int c = cz + k0 + cch;
            const float4 cw = *(const float4*)(conv_w + c * DCONV);
            const float  cb = conv_b[c];
            const __half* raw = (const __half*)(smem + (kc & 3) * RSTG);
            __half* amma = (__half*)(smem + AMMA_OFF);
            #pragma unroll 4
            for (int i = 0; i < 16; i++) {
                int r = cg * 16 + i;
                int rr = r + 3;
                float v = cb;
                v += __half2float(raw[(rr - 3) * 32 + cch]) * cw.x;
                v += __half2float(raw[(rr - 2) * 32 + cch]) * cw.y;
                v += __half2float(raw[(rr - 1) * 32 + cch]) * cw.z;
                v += __half2float(raw[(rr    ) * 32 + cch]) * cw.w;
                float s = v / (1.f + __expf(-v));
                __half h = __float2half(s);
                amma[r * 40 + cch] = h;
                xi[(size_t)(row0 + r) * DINNER + c] = h;
            }
        }
        __syncthreads();

        uint32_t abase = sb + AMMA_OFF;
        #pragma unroll
        for (int ks = 0; ks < 2; ks++) {
            uint32_t koff = (ks * 16 + lkb * 8) * 2;
            uint32_t ah[2][4];
            #pragma unroll
            for (int mi = 0; mi < 2; mi++)
                LDSM4(ah[mi], abase + (wm + mi * 16 + lrow) * 80 + koff);
            uint32_t bf[4][4];
            #pragma unroll
            for (int p = 0; p < 4; p++)
                LDSM4(bf[p], rawb + RAWA + (wn + p * 16 + lrow) * 80 + koff);
            #pragma unroll
            for (int mi = 0; mi < 2; mi++)
                #pragma unroll
                for (int p = 0; p < 4; p++)
                    #pragma unroll
                    for (int hb = 0; hb < 2; hb++)
                        MMA16816(acc[mi][p * 2 + hb], ah[mi], bf[p][hb], bf[p][hb + 2]);
        }
    }

    const int rb = row0 + wm + (lane >> 2);
    const int cb2 = wn + (lane & 3) * 2;
    #pragma unroll
    for (int mi = 0; mi < 2; mi++)
        #pragma unroll
        for (int ni = 0; ni < 8; ni++) {
            int c = cb2 + ni * 8;
            if (c >= DBC_W) continue;        // cols 96..127 are padding
            #pragma unroll
            for (int half = 0; half < 2; half++) {
                int r = rb + mi * 16 + half * 8;
                *(float2*)(Cf + (size_t)r * 128 + c) =
                    make_float2(acc[mi][ni][half * 2 + 0], acc[mi][ni][half * 2 + 1]);
            }
        }
}

// ---------------------------------------------------------------------------
// Split-K reduce: cols<64 -> dt fp16; cols 64..95 -> dbc fp32. Rest dead.
// ---------------------------------------------------------------------------
__global__ void reduce_dbc(const float* __restrict__ part,
                           float* __restrict__ dbc,
                           __half* __restrict__ dt) {
    int i = blockIdx.x * blockDim.x + threadIdx.x;
    int r = i >> 7, c = i & 127;
    if (c >= DBC_W) return;
    float s = 0.f;
    #pragma unroll
    for (int p = 0; p < KSPLIT; p++)
        s += part[(size_t)p * NTOK * 128 + i];
    if (c < DTRANK) dt[(size_t)r * DTRANK + c] = __float2half(s);
    else            dbc[(size_t)r * DBC_W + c] = s;
}

// ---------------------------------------------------------------------------
// Scan pass 1 (128 threads): segment transfer (sum delta, cvec)
// ---------------------------------------------------------------------------
#define SCHUNK 16
#define SSTG1  9216
__global__ __launch_bounds__(128, 1)
void scan_pass1(const float* __restrict__ dbc,
                const __half* __restrict__ delta,
                const __half* __restrict__ xi,
                const float* __restrict__ A_log,
                float* __restrict__ segsum,
                float* __restrict__ segc) {
    __shared__ char sbuf[4 * SSTG1];
    const uint32_t sb = smem_u32(sbuf);
    const int seg   = blockIdx.y;
    const int b     = blockIdx.x >> 4;
    const int cbase = (blockIdx.x & 15) * 128;
    const int tid   = threadIdx.x;
    const int c     = cbase + tid;
    const size_t tok0 = (size_t)b * LL + (size_t)seg * SEGLEN;

    float A[DSTATE];
    #pragma unroll
    for (int s = 0; s < DSTATE; s++) A[s] = -__expf(A_log[c * DSTATE + s]);
    const float a1 = A[0];
    bool pat = true;
    #pragma unroll
    for (int s = 0; s < DSTATE; s++)
        pat = pat && (fabsf(A[s] - (float)(s + 1) * a1) <= 1e-5f * fabsf(A[s]));

    float h[DSTATE];
    #pragma unroll
    for (int s = 0; s < DSTATE; s++) h[s] = 0.f;
    float sd = 0.f;

    auto stage_load = [&](int st, int l0) {
        uint32_t base = sb + st * SSTG1;
        #pragma unroll
        for (int u0 = 0; u0 < 5; u0++) {
            int u = u0 * 128 + tid;
            if (u >= 576) break;
            uint32_t dst; const void* src;
            if (u < 256) {
                int r = u >> 4, s = u & 15;
                dst = base + r * 256 + s * 16;
                src = delta + (tok0 + l0 + r) * DINNER + cbase + s * 8;
            } else if (u < 512) {
                int v = u - 256; int r = v >> 4, s = v & 15;
                dst = base + 4096 + r * 256 + s * 16;
                src = xi + (tok0 + l0 + r) * DINNER + cbase + s * 8;
            } else {
                int v = u - 512; int r = v >> 2, s = v & 3;
                dst = base + 8192 + r * 64 + s * 16;
                src = dbc + (tok0 + l0 + r) * DBC_W + DTRANK + s * 4;
            }
            cp16(dst, src);
        }
    };

    const int nch = SEGLEN / SCHUNK;
    stage_load(0, 0);          CP_COMMIT();
    stage_load(1, SCHUNK);     CP_COMMIT();
    stage_load(2, 2 * SCHUNK); CP_COMMIT();

    for (int ck = 0; ck < nch; ck++) {
        CP_WAIT(2);
        __syncthreads();
        if (ck + 3 < nch) stage_load((ck + 3) & 3, (ck + 3) * SCHUNK);
        CP_COMMIT();

        const char* base = sbuf + (ck & 3) * SSTG1;
        const __half* sd16 = (const __half*)(base);
        const __half* sxi  = (const __half*)(base + 4096);
        const float*  sB   = (const float*)(base + 8192);

        #pragma unroll 4
        for (int l = 0; l < SCHUNK; l++) {
            float d  = __half2float(sd16[l * 128 + tid]);
            float xv = __half2float(sxi[l * 128 + tid]);
            const float* Bv = sB + l * 16;
            float dx = d * xv;
            if (pat) {
                float P[DSTATE];
                exp_powers(__expf(d * a1), P);
                #pragma unroll
                for (int s = 0; s < DSTATE; s++)
                    h[s] = P[s] * h[s] + dx * Bv[s];
            } else {
                #pragma unroll
                for (int s = 0; s < DSTATE; s++)
                    h[s] = __expf(d * A[s]) * h[s] + dx * Bv[s];
            }
            sd += d;
        }
        __syncthreads();
    }

    size_t bc = (size_t)seg * BB * DINNER + (size_t)b * DINNER + c;
    segsum[bc] = sd;
    #pragma unroll
    for (int s = 0; s < DSTATE; s++)
        segc[bc * DSTATE + s] = h[s];
}

// ---------------------------------------------------------------------------
// Scan pass 2 (128 threads): fold prefix, run SEGLEN steps, gated output.
// ---------------------------------------------------------------------------
#define SSTG2  14336
__global__ __launch_bounds__(128, 1)
void scan_pass2(const float* __restrict__ dbc,
                const __half* __restrict__ delta,
                const __half* __restrict__ xi,
                const __half* __restrict__ xz,
                const float* __restrict__ A_log,
                const float* __restrict__ Dp,
                const float* __restrict__ segsum,
                const float* __restrict__ segc,
                __half* __restrict__ gout) {
    __shared__ char sbuf[4 * SSTG2];
    const uint32_t sb = smem_u32(sbuf);
    const int seg   = blockIdx.y;
    const int b     = blockIdx.x >> 4;
    const int cbase = (blockIdx.x & 15) * 128;
    const int tid   = threadIdx.x;
    const int c     = cbase + tid;
    const size_t tok0 = (size_t)b * LL + (size_t)seg * SEGLEN;

    float A[DSTATE];
    #pragma unroll
    for (int s = 0; s < DSTATE; s++) A[s] = -__expf(A_log[c * DSTATE + s]);
    const float a1 = A[0];
    bool pat = true;
    #pragma unroll
    for (int s = 0; s < DSTATE; s++)
        pat = pat && (fabsf(A[s] - (float)(s + 1) * a1) <= 1e-5f * fabsf(A[s]));
    const float Dv = Dp[c];

    float h[DSTATE];
    #pragma unroll
    for (int s = 0; s < DSTATE; s++) h[s] = 0.f;
    for (int j = 0; j < seg; j++) {
        size_t bc = (size_t)j * BB * DINNER + (size_t)b * DINNER + c;
        float sdj = segsum[bc];
        if (pat) {
            float P[DSTATE];
            exp_powers(__expf(sdj * a1), P);
            #pragma unroll
            for (int s = 0; s < DSTATE; s++)
                h[s] = P[s] * h[s] + segc[bc * DSTATE + s];
        } else {
            #pragma unroll
            for (int s = 0; s < DSTATE; s++)
                h[s] = __expf(sdj * A[s]) * h[s] + segc[bc * DSTATE + s];
        }
    }

    auto stage_load = [&](int st, int l0) {
        uint32_t base = sb + st * SSTG2;
        #pragma unroll
        for (int u0 = 0; u0 < 7; u0++) {
            int u = u0 * 128 + tid;
            if (u >= 896) break;
            uint32_t dst; const void* src;
            if (u < 256) {
                int r = u >> 4, s = u & 15;
                dst = base + r * 256 + s * 16;
                src = delta + (tok0 + l0 + r) * DINNER + cbase + s * 8;
            } else if (u < 512) {
                int v = u - 256; int r = v >> 4, s = v & 15;
                dst = base + 4096 + r * 256 + s * 16;
                src = xz + (tok0 + l0 + r) * (2 * DINNER) + DINNER + cbase + s * 8;
            } else if (u < 768) {
                int v = u - 512; int r = v >> 4, s = v & 15;
                dst = base + 8192 + r * 256 + s * 16;
                src = xi + (tok0 + l0 + r) * DINNER + cbase + s * 8;
            } else {
                int v = u - 768; int r = v >> 3, s = v & 7;
                dst = base + 12288 + r * 128 + s * 16;
                src = dbc + (tok0 + l0 + r) * DBC_W + DTRANK + s * 4;
            }
            cp16(dst, src);
        }
    };

    const int nch = SEGLEN / SCHUNK;
    stage_load(0, 0);          CP_COMMIT();
    stage_load(1, SCHUNK);     CP_COMMIT();
    stage_load(2, 2 * SCHUNK); CP_COMMIT();

    for (int ck = 0; ck < nch; ck++) {
        CP_WAIT(2);
        __syncthreads();
        if (ck + 3 < nch) stage_load((ck + 3) & 3, (ck + 3) * SCHUNK);
        CP_COMMIT();

        const char* base = sbuf + (ck & 3) * SSTG2;
        const __half* sd16 = (const __half*)(base);
        const __half* ssg  = (const __half*)(base + 4096);
        const __half* sxi  = (const __half*)(base + 8192);
        const float*  sbc  = (const float*)(base + 12288);
        const int l0 = ck * SCHUNK;

        #pragma unroll 4
        for (int l = 0; l < SCHUNK; l++) {
            float d  = __half2float(sd16[l * 128 + tid]);
            float sg = __half2float(ssg[l * 128 + tid]);
            float xv = __half2float(sxi[l * 128 + tid]);
            const float* Bv = sbc + l * 32;
            const float* Cv = Bv + DSTATE;
            float dx = d * xv;
            float y = 0.f;
            if (pat) {
                float P[DSTATE];
                exp_powers(__expf(d * a1), P);
                #pragma unroll
                for (int s = 0; s < DSTATE; s++) {
                    h[s] = P[s] * h[s] + dx * Bv[s];
                    y = fmaf(h[s], Cv[s], y);
                }
            } else {
                #pragma unroll
                for (int s = 0; s < DSTATE; s++) {
                    h[s] = __expf(d * A[s]) * h[s] + dx * Bv[s];
                    y = fmaf(h[s], Cv[s], y);
                }
            }
            float g = y + xv * Dv;
            gout[(tok0 + l0 + l) * DINNER + c] = __float2half(g * sg);
        }
        __syncthreads();
    }
}

// ---------------------------------------------------------------------------
// Launch
// ---------------------------------------------------------------------------
extern "C" void kernel_launch(void* const* d_in, const int* in_sizes, int n_in,
                              void* d_out, int out_size) {
    const float* x        = (const float*)d_in[0];
    const float* rms_w    = (const float*)d_in[1];
    const float* in_proj  = (const float*)d_in[2];
    const float* conv_w   = (const float*)d_in[3];
    const float* conv_b   = (const float*)d_in[4];
    const float* x_proj   = (const float*)d_in[5];
    const float* dt_w     = (const float*)d_in[6];
    const float* dt_b     = (const float*)d_in[7];
    const float* A_log    = (const float*)d_in[8];
    const float* Dp       = (const float*)d_in[9];
    const float* out_proj = (const float*)d_in[10];
    float* out = (float*)d_out;

    float *dbc, *dbcp, *segsum, *segc;
    __half *xz, *delta, *xn, *xi, *dt, *gg, *ipT, *xpT, *dwT, *opT;
    cudaGetSymbolAddress((void**)&xz,     g_xz);
    cudaGetSymbolAddress((void**)&dbc,    g_dbc);
    cudaGetSymbolAddress((void**)&dbcp,   g_dbcp);
    cudaGetSymbolAddress((void**)&delta,  g_delta);
    cudaGetSymbolAddress((void**)&xn,     g_xn);
    cudaGetSymbolAddress((void**)&xi,     g_xi);
    cudaGetSymbolAddress((void**)&dt,     g_dt);
    cudaGetSymbolAddress((void**)&gg,     g_g);
    cudaGetSymbolAddress((void**)&segsum, g_segsum);
    cudaGetSymbolAddress((void**)&segc,   g_segc);
    cudaGetSymbolAddress((void**)&ipT,    g_ipT);
    cudaGetSymbolAddress((void**)&xpT,    g_xpT);
    cudaGetSymbolAddress((void**)&dwT,    g_dwT);
    cudaGetSymbolAddress((void**)&opT,    g_opT);

    cudaFuncSetAttribute(mma_gemm<1>, cudaFuncAttributeMaxDynamicSharedMemorySize, SMEM_GEMM);
    cudaFuncSetAttribute(mma_gemm<2>, cudaFuncAttributeMaxDynamicSharedMemorySize, SMEM_GEMM);
    cudaFuncSetAttribute(mma_gemm<4>, cudaFuncAttributeMaxDynamicSharedMemorySize, SMEM_GEMM);
    cudaFuncSetAttribute(gemm2_fused, cudaFuncAttributeMaxDynamicSharedMemorySize, SMEM_G2);

    // 0+1. fused prep: 4 weight transposes + rmsnorm in ONE launch
    prep_kernel<<<6464 + NTOK, 256>>>(in_proj, x_proj, dt_w, out_proj,
                                      ipT, xpT, dwT, opT, x, rms_w, xn);

    // 2. xz = xn @ in_proj -> fp16 (z half stored as silu(z))
    {
        dim3 grid(2 * DINNER / 128, NTOK / 128);
        mma_gemm<4><<<grid, 256, SMEM_GEMM>>>(xn, ipT, xz, 2 * DINNER, DIM, DIM,
                                              nullptr);
    }

    // 3+4. conv+silu fused into split-K dbc GEMM (writes xi + partials) + reduce
    {
        dim3 grid(1, NTOK / 128, KSPLIT);
        gemm2_fused<<<grid, 256, SMEM_G2>>>(xz, xpT, conv_w, conv_b, xi, dbcp);
        reduce_dbc<<<NTOK * 128 / 256, 256>>>(dbcp, dbc, dt);
    }

    // 5. delta = softplus(dt @ dt_w + dt_b) -> fp16
    {
        dim3 grid(DINNER / 128, NTOK / 128);
        mma_gemm<1><<<grid, 256, SMEM_GEMM>>>(dt, dwT, delta, DINNER, DTRANK, DTRANK,
                                              dt_b);
    }

    // 6. parallel selective scan (2 passes, 128-thread blocks)
    {
        dim3 g1(BB * (DINNER / 128), NSEG - 1);
        scan_pass1<<<g1, 128>>>(dbc, delta, xi, A_log, segsum, segc);
        dim3 g2(BB * (DINNER / 128), NSEG);
        scan_pass2<<<g2, 128>>>(dbc, delta, xi, xz, A_log, Dp, segsum, segc, gg);
    }

    // 7. out = x + gated @ out_proj
    {
        dim3 grid(DIM / 128, NTOK / 128);
        mma_gemm<2><<<grid, 256, SMEM_GEMM>>>(gg, opT, out, DIM, DINNER, DINNER,
                                              x);
    }
}

// round 16
// speedup vs baseline: 1.0604x; 1.0604x over previous
#include <cuda_runtime.h>
#include <cuda_fp16.h>
#include <math.h>
#include <stdint.h>

// ---------------------------------------------------------------------------
// Mamba block: B=4, L=2048, dim=1024, d_inner=2048, d_state=16, K=4, dt_rank=64
// Baseline sm_103 PTX -> ldmatrix + mma.sync fp16 HMMA (fp32 accum).
// System is effective-BW bound (~2 TB/s): optimize by CUTTING BYTES while
// keeping full launch waves (>=2 CTAs/SM, >=1 full wave per kernel).
// R16 = R13 winner (KSPLIT=4, 256-block gemm2) + R15's dead-byte cuts only.
// ---------------------------------------------------------------------------
#define BB      4
#define LL      2048
#define DIM     1024
#define DINNER  2048
#define DSTATE  16
#define DCONV   4
#define DTRANK  64
#define NTOK    (BB * LL)              // 8192
#define DBC_W   (DTRANK + 2 * DSTATE)  // 96
#define KSPLIT  4
#define NSEG    8
#define SEGLEN  (LL / NSEG)            // 256

// ---------------------------------------------------------------------------
// Scratch (device globals; zero-initialized)
// ---------------------------------------------------------------------------
__device__ __half g_xz[(size_t)NTOK * 2 * DINNER];       // z half stores silu(z)
__device__ float  g_dbc[(size_t)NTOK * DBC_W];
__device__ float  g_dbcp[(size_t)KSPLIT * NTOK * 128];
__device__ __half g_delta[(size_t)NTOK * DINNER];
__device__ __half g_xn[(size_t)NTOK * DIM];
__device__ __half g_xi[(size_t)NTOK * DINNER];
__device__ __half g_dt[(size_t)NTOK * DTRANK];
__device__ __half g_g[(size_t)NTOK * DINNER];
__device__ float  g_segsum[(size_t)NSEG * BB * DINNER];
__device__ float  g_segc[(size_t)NSEG * BB * DINNER * DSTATE];
__device__ __half g_ipT[(size_t)(2 * DINNER) * DIM];
__device__ __half g_xpT[(size_t)128 * DINNER];
__device__ __half g_dwT[(size_t)DINNER * DTRANK];
__device__ __half g_opT[(size_t)DIM * DINNER];

// ---------------------------------------------------------------------------
// PTX helpers
// ---------------------------------------------------------------------------
__device__ __forceinline__ uint32_t smem_u32(const void* p) {
    uint32_t a;
    asm("{ .reg .u64 t; cvta.to.shared.u64 t, %1; cvt.u32.u64 %0, t; }" : "=r"(a) : "l"(p));
    return a;
}
__device__ __forceinline__ void cp16(uint32_t dst, const void* src) {
    asm volatile("cp.async.cg.shared.global [%0], [%1], 16;" :: "r"(dst), "l"(src));
}
#define CP_COMMIT() asm volatile("cp.async.commit_group;" ::: "memory")
#define CP_WAIT(n)  asm volatile("cp.async.wait_group %0;" :: "n"(n) : "memory")

#define LDSM4(r, a) \
    asm volatile("ldmatrix.sync.aligned.m8n8.x4.shared.b16 {%0,%1,%2,%3}, [%4];" \
        : "=r"((r)[0]), "=r"((r)[1]), "=r"((r)[2]), "=r"((r)[3]) : "r"(a))

#define MMA16816(d, a, b0, b1) \
    asm volatile("mma.sync.aligned.m16n8k16.row.col.f32.f16.f16.f32 " \
        "{%0,%1,%2,%3}, {%4,%5,%6,%7}, {%8,%9}, {%0,%1,%2,%3};" \
        : "+f"((d)[0]), "+f"((d)[1]), "+f"((d)[2]), "+f"((d)[3]) \
        : "r"((a)[0]), "r"((a)[1]), "r"((a)[2]), "r"((a)[3]), "r"(b0), "r"(b1))

__device__ __forceinline__ void exp_powers(float E, float* P) {
    float E2 = E * E, E4 = E2 * E2, E8 = E4 * E4;
    P[0]=E;      P[1]=E2;      P[2]=E2*E;     P[3]=E4;
    P[4]=E4*E;   P[5]=E4*E2;   P[6]=E4*P[2];  P[7]=E8;
    P[8]=E8*E;   P[9]=E8*E2;   P[10]=E8*P[2]; P[11]=E8*E4;
    P[12]=E8*P[4]; P[13]=E8*P[5]; P[14]=E8*P[6]; P[15]=E8*E8;
}

// ---------------------------------------------------------------------------
// Fused prep: weight transposes + rmsnorm, one grid.
// ---------------------------------------------------------------------------
__device__ __forceinline__ void transpose_tile(const float* __restrict__ W,
                                               __half* __restrict__ T,
                                               int R, int C, int cb, int rb) {
    __shared__ float t[32][33];
    const int tx = threadIdx.x & 31, ty = threadIdx.x >> 5;
    int c0 = cb * 32, r0 = rb * 32;
    int c = c0 + tx;
    for (int i = ty; i < 32; i += 8) {
        int r = r0 + i;
        if (r < R && c < C) t[i][tx] = W[(size_t)r * C + c];
    }
    __syncthreads();
    int k = r0 + tx;
    for (int i = ty; i < 32; i += 8) {
        int n = c0 + i;
        if (n < C && k < R)
            T[(size_t)n * R + k] = __float2half(t[tx][i]);
    }
}

__global__ void __launch_bounds__(256)
prep_kernel(const float* __restrict__ in_proj, const float* __restrict__ x_proj,
            const float* __restrict__ dt_w,    const float* __restrict__ out_proj,
            __half* __restrict__ ipT, __half* __restrict__ xpT,
            __half* __restrict__ dwT, __half* __restrict__ opT,
            const float* __restrict__ x, const float* __restrict__ rms_w,
            __half* __restrict__ xn) {
    int bid = blockIdx.x;
    if (bid < 4096) {
        transpose_tile(in_proj, ipT, DIM, 2 * DINNER, bid & 127, bid >> 7);
    } else if (bid < 4288) {
        int i = bid - 4096;
        transpose_tile(x_proj, xpT, DINNER, DBC_W, i % 3, i / 3);
    } else if (bid < 4416) {
        int i = bid - 4288;
        transpose_tile(dt_w, dwT, DTRANK, DINNER, i & 63, i >> 6);
    } else if (bid < 6464) {
        int i = bid - 4416;
        transpose_tile(out_proj, opT, DINNER, DIM, i & 31, i >> 5);
    } else {
        int t = bid - 6464;
        const float* xr = x + (size_t)t * DIM;
        float s = 0.f;
        for (int i = threadIdx.x; i < DIM; i += 256) { float v = xr[i]; s += v * v; }
        #pragma unroll
        for (int off = 16; off > 0; off >>= 1) s += __shfl_xor_sync(0xffffffffu, s, off);
        __shared__ float red[8];
        int wid = threadIdx.x >> 5;
        if ((threadIdx.x & 31) == 0) red[wid] = s;
        __syncthreads();
        __shared__ float sscale;
        if (threadIdx.x == 0) {
            float tot = 0.f;
            #pragma unroll
            for (int i = 0; i < 8; i++) tot += red[i];
            sscale = rsqrtf(tot * (1.0f / DIM) + 1e-5f);
        }
        __syncthreads();
        float scale = sscale;
        for (int i = threadIdx.x * 2; i < DIM; i += 512) {
            float2 v = *(const float2*)(xr + i);
            float2 wv = *(const float2*)(rms_w + i);
            *(__half2*)(xn + (size_t)t * DIM + i) =
                __floats2half2_rn(v.x * scale * wv.x, v.y * scale * wv.y);
        }
    }
}

// ---------------------------------------------------------------------------
// mma.sync fp16 GEMM (128x128, 256 thr, 4-stage cp.async, 2 CTAs/SM).
// MODE 1: softplus(+bias) -> fp16  2: +res -> fp32
// MODE 4: fp16 out, silu applied to columns >= DINNER (the z half)
// ---------------------------------------------------------------------------
#define TSB   10240
#define STGB  (2 * TSB)
#define SMEM_GEMM (4 * STGB)          // 81920

template<int MODE>
__global__ void __launch_bounds__(256)
mma_gemm(const __half* __restrict__ A, const __half* __restrict__ B,
         void* __restrict__ Cv, int N, int K, int ld,
         const float* __restrict__ extra) {
    extern __shared__ char smem[];
    const uint32_t sb = smem_u32(smem);
    const int tid  = threadIdx.x;
    const int lane = tid & 31;
    const int wid  = tid >> 5;
    const int wm = (wid & 3) * 32;
    const int wn = (wid >> 2) * 64;
    const int row0 = blockIdx.y * 128;
    const int col0 = blockIdx.x * 128;
    const int nch = K >> 5;

    float*  Cf = (float*)Cv;
    __half* Ch = (__half*)Cv;

    auto load_stage = [&](int st, int k0) {
        uint32_t base = sb + st * STGB;
        #pragma unroll
        for (int u = 0; u < 2; u++) {
            int i = u * 256 + tid;
            int r = i >> 2, seg = i & 3;
            uint32_t d = base + r * 80 + seg * 16;
            cp16(d,       A + (size_t)(row0 + r) * ld + k0 + seg * 8);
            cp16(d + TSB, B + (size_t)(col0 + r) * ld + k0 + seg * 8);
        }
    };

    float acc[2][8][4];
    #pragma unroll
    for (int mi = 0; mi < 2; mi++)
        #pragma unroll
        for (int ni = 0; ni < 8; ni++)
            #pragma unroll
            for (int q = 0; q < 4; q++) acc[mi][ni][q] = 0.f;

    const int lrow = lane & 15;
    const int lkb  = lane >> 4;

    load_stage(0, 0);                      CP_COMMIT();
    if (nch > 1) load_stage(1, 32);        CP_COMMIT();
    if (nch > 2) load_stage(2, 64);        CP_COMMIT();

    for (int kc = 0; kc < nch; kc++) {
        CP_WAIT(2);
        __syncthreads();
        if (kc + 3 < nch) load_stage((kc + 3) & 3, (kc + 3) << 5);
        CP_COMMIT();

        uint32_t base = sb + (kc & 3) * STGB;
        #pragma unroll
        for (int ks = 0; ks < 2; ks++) {
            uint32_t koff = (ks * 16 + lkb * 8) * 2;
            uint32_t ah[2][4];
            #pragma unroll
            for (int mi = 0; mi < 2; mi++)
                LDSM4(ah[mi], base + (wm + mi * 16 + lrow) * 80 + koff);
            uint32_t bf[4][4];
            #pragma unroll
            for (int p = 0; p < 4; p++)
                LDSM4(bf[p], base + TSB + (wn + p * 16 + lrow) * 80 + koff);
            #pragma unroll
            for (int mi = 0; mi < 2; mi++)
                #pragma unroll
                for (int p = 0; p < 4; p++)
                    #pragma unroll
                    for (int hb = 0; hb < 2; hb++)
                        MMA16816(acc[mi][p * 2 + hb], ah[mi], bf[p][hb], bf[p][hb + 2]);
        }
        __syncthreads();
    }

    const int rb = row0 + wm + (lane >> 2);
    const int cb = col0 + wn + (lane & 3) * 2;
    #pragma unroll
    for (int mi = 0; mi < 2; mi++)
        #pragma unroll
        for (int ni = 0; ni < 8; ni++) {
            int c = cb + ni * 8;
            if (c >= N) continue;
            #pragma unroll
            for (int half = 0; half < 2; half++) {
                int r = rb + mi * 16 + half * 8;
                float v0 = acc[mi][ni][half * 2 + 0];
                float v1 = acc[mi][ni][half * 2 + 1];
                if (MODE == 1) {
                    v0 += extra[c];     v1 += extra[c + 1];
                    v0 = (v0 > 20.f) ? v0 : log1pf(__expf(v0));
                    v1 = (v1 > 20.f) ? v1 : log1pf(__expf(v1));
                } else if (MODE == 2) {
                    const float2 res = *(const float2*)(extra + (size_t)r * N + c);
                    v0 += res.x; v1 += res.y;
                } else if (MODE == 4) {
                    if (c >= DINNER) {   // z half -> store silu(z)
                        v0 = v0 / (1.f + __expf(-v0));
                        v1 = v1 / (1.f + __expf(-v1));
                    }
                }
                if (MODE == 2)
                    *(float2*)(Cf + (size_t)r * N + c) = make_float2(v0, v1);
                else
                    *(__half2*)(Ch + (size_t)r * N + c) = __floats2half2_rn(v0, v1);
            }
        }
}

// ---------------------------------------------------------------------------
// GEMM2 fused: dbc partials = conv_silu(xz_x) @ xpT^T, AND writes xi.
// grid (1, NTOK/128, KSPLIT=4): 256 blocks (~2 waves), K=512 per z.
// Partials: only cols < 96 stored (96..127 are zero-weight padding).
// ---------------------------------------------------------------------------
#define RAWA  8384                    // 131 rows x 64 B
#define RSTG  (RAWA + TSB)            // 18624 per stage
#define AMMA_OFF (4 * RSTG)           // 74496
#define SMEM_G2  (AMMA_OFF + TSB)     // 84736

__global__ void __launch_bounds__(256)
gemm2_fused(const __half* __restrict__ xz,
            const __half* __restrict__ xpT,
            const float* __restrict__ conv_w,
            const float* __restrict__ conv_b,
            __half* __restrict__ xi,
            float* __restrict__ dbcp) {
    extern __shared__ char smem[];
    const uint32_t sb = smem_u32(smem);
    const int tid  = threadIdx.x;
    const int lane = tid & 31;
    const int wid  = tid >> 5;
    const int wm = (wid & 3) * 32;
    const int wn = (wid >> 2) * 64;
    const int row0 = blockIdx.y * 128;
    const int cz   = blockIdx.z * (DINNER / KSPLIT);   // 512 per z
    const bool first = (row0 & (LL - 1)) == 0;
    const int nch = (DINNER / KSPLIT) >> 5;            // 16

    float* Cf = dbcp + (size_t)blockIdx.z * NTOK * 128;

    auto load_stage = [&](int st, int k0) {
        uint32_t base = sb + st * RSTG;
        #pragma unroll
        for (int u0 = 0; u0 < 5; u0++) {
            int u = u0 * 256 + tid;
            if (u >= 1036) break;
            if (u < 524) {
                int r = u >> 2, seg = u & 3;
                uint32_t d = base + r * 64 + seg * 16;
                if (first && r < 3) {
                    *(uint4*)(smem + (d - sb)) = make_uint4(0, 0, 0, 0);
                } else {
                    cp16(d, xz + (size_t)(row0 - 3 + r) * (2 * DINNER) + cz + k0 + seg * 8);
                }
            } else {
                int v = u - 524;
                int r = v >> 2, seg = v & 3;
                cp16(base + RAWA + r * 80 + seg * 16,
                     xpT + (size_t)r * DINNER + cz + k0 + seg * 8);
            }
        }
    };

    float acc[2][8][4];
    #pragma unroll
    for (int mi = 0; mi < 2; mi++)
        #pragma unroll
        for (int ni = 0; ni < 8; ni++)
            #pragma unroll
            for (int q = 0; q < 4; q++) acc[mi][ni][q] = 0.f;

    const int lrow = lane & 15;
    const int lkb  = lane >> 4;
    const int cch  = tid & 31;
    const int cg   = tid >> 5;

    load_stage(0, 0);   CP_COMMIT();
    load_stage(1, 32);  CP_COMMIT();
    load_stage(2, 64);  CP_COMMIT();

    for (int kc = 0; kc < nch; kc++) {
        CP_WAIT(2);
        __syncthreads();
        if (kc + 3 < nch) load_stage((kc + 3) & 3, (kc + 3) << 5);
        CP_COMMIT();

        const int k0 = kc << 5;
        uint32_t rawb = sb + (kc & 3) * RSTG;

        {
            const int c = cz + k0 + cch;
            const float4 cw = *(const float4*)(conv_w + c * DCONV);
            const float  cb = conv_b[c];
            const __half* raw = (const __half*)(smem + (kc & 3) * RSTG);
            __half* amma = (__half*)(smem + AMMA_OFF);
            #pragma unroll 4
            for (int i = 0; i < 16; i++) {
                int r = cg * 16 + i;
                int rr = r + 3;
                float v = cb;
                v += __half2float(raw[(rr - 3) * 32 + cch]) * cw.x;
                v += __half2float(raw[(rr - 2) * 32 + cch]) * cw.y;
                v += __half2float(raw[(rr - 1) * 32 + cch]) * cw.z;
                v += __half2float(raw[(rr    ) * 32 + cch]) * cw.w;
                float s = v / (1.f + __expf(-v));
                __half h = __float2half(s);
                amma[r * 40 + cch] = h;
                xi[(size_t)(row0 + r) * DINNER + c] = h;
            }
        }
        __syncthreads();

        uint32_t abase = sb + AMMA_OFF;
        #pragma unroll
        for (int ks = 0; ks < 2; ks++) {
            uint32_t koff = (ks * 16 + lkb * 8) * 2;
            uint32_t ah[2][4];
            #pragma unroll
            for (int mi = 0; mi < 2; mi++)
                LDSM4(ah[mi], abase + (wm + mi * 16 + lrow) * 80 + koff);
            uint32_t bf[4][4];
            #pragma unroll
            for (int p = 0; p < 4; p++)
                LDSM4(bf[p], rawb + RAWA + (wn + p * 16 + lrow) * 80 + koff);
            #pragma unroll
            for (int mi = 0; mi < 2; mi++)
                #pragma unroll
                for (int p = 0; p < 4; p++)
                    #pragma unroll
                    for (int hb = 0; hb < 2; hb++)
                        MMA16816(acc[mi][p * 2 + hb], ah[mi], bf[p][hb], bf[p][hb + 2]);
        }
    }

    const int rb = row0 + wm + (lane >> 2);
    const int cb2 = wn + (lane & 3) * 2;
    #pragma unroll
    for (int mi = 0; mi < 2; mi++)
        #pragma unroll
        for (int ni = 0; ni < 8; ni++) {
            int c = cb2 + ni * 8;
            if (c >= DBC_W) continue;        // cols 96..127 are padding
            #pragma unroll
            for (int half = 0; half < 2; half++) {
                int r = rb + mi * 16 + half * 8;
                *(float2*)(Cf + (size_t)r * 128 + c) =
                    make_float2(acc[mi][ni][half * 2 + 0], acc[mi][ni][half * 2 + 1]);
            }
        }
}

// ---------------------------------------------------------------------------
// Split-K reduce: cols<64 -> dt fp16; cols 64..95 -> dbc fp32. Rest dead.
// ---------------------------------------------------------------------------
__global__ void reduce_dbc(const float* __restrict__ part,
                           float* __restrict__ dbc,
                           __half* __restrict__ dt) {
    int i = blockIdx.x * blockDim.x + threadIdx.x;
    int r = i >> 7, c = i & 127;
    if (c >= DBC_W) return;
    float s = 0.f;
    #pragma unroll
    for (int p = 0; p < KSPLIT; p++)
        s += part[(size_t)p * NTOK * 128 + i];
    if (c < DTRANK) dt[(size_t)r * DTRANK + c] = __float2half(s);
    else            dbc[(size_t)r * DBC_W + c] = s;
}

// ---------------------------------------------------------------------------
// Scan pass 1 (128 threads): segment transfer (sum delta, cvec)
// ---------------------------------------------------------------------------
#define SCHUNK 16
#define SSTG1  9216
__global__ __launch_bounds__(128, 1)
void scan_pass1(const float* __restrict__ dbc,
                const __half* __restrict__ delta,
                const __half* __restrict__ xi,
                const float* __restrict__ A_log,
                float* __restrict__ segsum,
                float* __restrict__ segc) {
    __shared__ char sbuf[4 * SSTG1];
    const uint32_t sb = smem_u32(sbuf);
    const int seg   = blockIdx.y;
    const int b     = blockIdx.x >> 4;
    const int cbase = (blockIdx.x & 15) * 128;
    const int tid   = threadIdx.x;
    const int c     = cbase + tid;
    const size_t tok0 = (size_t)b * LL + (size_t)seg * SEGLEN;

    float A[DSTATE];
    #pragma unroll
    for (int s = 0; s < DSTATE; s++) A[s] = -__expf(A_log[c * DSTATE + s]);
    const float a1 = A[0];
    bool pat = true;
    #pragma unroll
    for (int s = 0; s < DSTATE; s++)
        pat = pat && (fabsf(A[s] - (float)(s + 1) * a1) <= 1e-5f * fabsf(A[s]));

    float h[DSTATE];
    #pragma unroll
    for (int s = 0; s < DSTATE; s++) h[s] = 0.f;
    float sd = 0.f;

    auto stage_load = [&](int st, int l0) {
        uint32_t base = sb + st * SSTG1;
        #pragma unroll
        for (int u0 = 0; u0 < 5; u0++) {
            int u = u0 * 128 + tid;
            if (u >= 576) break;
            uint32_t dst; const void* src;
            if (u < 256) {
                int r = u >> 4, s = u & 15;
                dst = base + r * 256 + s * 16;
                src = delta + (tok0 + l0 + r) * DINNER + cbase + s * 8;
            } else if (u < 512) {
                int v = u - 256; int r = v >> 4, s = v & 15;
                dst = base + 4096 + r * 256 + s * 16;
                src = xi + (tok0 + l0 + r) * DINNER + cbase + s * 8;
            } else {
                int v = u - 512; int r = v >> 2, s = v & 3;
                dst = base + 8192 + r * 64 + s * 16;
                src = dbc + (tok0 + l0 + r) * DBC_W + DTRANK + s * 4;
            }
            cp16(dst, src);
        }
    };

    const int nch = SEGLEN / SCHUNK;
    stage_load(0, 0);          CP_COMMIT();
    stage_load(1, SCHUNK);     CP_COMMIT();
    stage_load(2, 2 * SCHUNK); CP_COMMIT();

    for (int ck = 0; ck < nch; ck++) {
        CP_WAIT(2);
        __syncthreads();
        if (ck + 3 < nch) stage_load((ck + 3) & 3, (ck + 3) * SCHUNK);
        CP_COMMIT();

        const char* base = sbuf + (ck & 3) * SSTG1;
        const __half* sd16 = (const __half*)(base);
        const __half* sxi  = (const __half*)(base + 4096);
        const float*  sB   = (const float*)(base + 8192);

        #pragma unroll 4
        for (int l = 0; l < SCHUNK; l++) {
            float d  = __half2float(sd16[l * 128 + tid]);
            float xv = __half2float(sxi[l * 128 + tid]);
            const float* Bv = sB + l * 16;
            float dx = d * xv;
            if (pat) {
                float P[DSTATE];
                exp_powers(__expf(d * a1), P);
                #pragma unroll
                for (int s = 0; s < DSTATE; s++)
                    h[s] = P[s] * h[s] + dx * Bv[s];
            } else {
                #pragma unroll
                for (int s = 0; s < DSTATE; s++)
                    h[s] = __expf(d * A[s]) * h[s] + dx * Bv[s];
            }
            sd += d;
        }
        __syncthreads();
    }

    size_t bc = (size_t)seg * BB * DINNER + (size_t)b * DINNER + c;
    segsum[bc] = sd;
    #pragma unroll
    for (int s = 0; s < DSTATE; s++)
        segc[bc * DSTATE + s] = h[s];
}

// ---------------------------------------------------------------------------
// Scan pass 2 (128 threads): fold prefix, run SEGLEN steps, gated output.
// ---------------------------------------------------------------------------
#define SSTG2  14336
__global__ __launch_bounds__(128, 1)
void scan_pass2(const float* __restrict__ dbc,
                const __half* __restrict__ delta,
                const __half* __restrict__ xi,
                const __half* __restrict__ xz,
                const float* __restrict__ A_log,
                const float* __restrict__ Dp,
                const float* __restrict__ segsum,
                const float* __restrict__ segc,
                __half* __restrict__ gout) {
    __shared__ char sbuf[4 * SSTG2];
    const uint32_t sb = smem_u32(sbuf);
    const int seg   = blockIdx.y;
    const int b     = blockIdx.x >> 4;
    const int cbase = (blockIdx.x & 15) * 128;
    const int tid   = threadIdx.x;
    const int c     = cbase + tid;
    const size_t tok0 = (size_t)b * LL + (size_t)seg * SEGLEN;

    float A[DSTATE];
    #pragma unroll
    for (int s = 0; s < DSTATE; s++) A[s] = -__expf(A_log[c * DSTATE + s]);
    const float a1 = A[0];
    bool pat = true;
    #pragma unroll
    for (int s = 0; s < DSTATE; s++)
        pat = pat && (fabsf(A[s] - (float)(s + 1) * a1) <= 1e-5f * fabsf(A[s]));
    const float Dv = Dp[c];

    float h[DSTATE];
    #pragma unroll
    for (int s = 0; s < DSTATE; s++) h[s] = 0.f;
    for (int j = 0; j < seg; j++) {
        size_t bc = (size_t)j * BB * DINNER + (size_t)b * DINNER + c;
        float sdj = segsum[bc];
        if (pat) {
            float P[DSTATE];
            exp_powers(__expf(sdj * a1), P);
            #pragma unroll
            for (int s = 0; s < DSTATE; s++)
                h[s] = P[s] * h[s] + segc[bc * DSTATE + s];
        } else {
            #pragma unroll
            for (int s = 0; s < DSTATE; s++)
                h[s] = __expf(sdj * A[s]) * h[s] + segc[bc * DSTATE + s];
        }
    }

    auto stage_load = [&](int st, int l0) {
        uint32_t base = sb + st * SSTG2;
        #pragma unroll
        for (int u0 = 0; u0 < 7; u0++) {
            int u = u0 * 128 + tid;
            if (u >= 896) break;
            uint32_t dst; const void* src;
            if (u < 256) {
                int r = u >> 4, s = u & 15;
                dst = base + r * 256 + s * 16;
                src = delta + (tok0 + l0 + r) * DINNER + cbase + s * 8;
            } else if (u < 512) {
                int v = u - 256; int r = v >> 4, s = v & 15;
                dst = base + 4096 + r * 256 + s * 16;
                src = xz + (tok0 + l0 + r) * (2 * DINNER) + DINNER + cbase + s * 8;
            } else if (u < 768) {
                int v = u - 512; int r = v >> 4, s = v & 15;
                dst = base + 8192 + r * 256 + s * 16;
                src = xi + (tok0 + l0 + r) * DINNER + cbase + s * 8;
            } else {
                int v = u - 768; int r = v >> 3, s = v & 7;
                dst = base + 12288 + r * 128 + s * 16;
                src = dbc + (tok0 + l0 + r) * DBC_W + DTRANK + s * 4;
            }
            cp16(dst, src);
        }
    };

    const int nch = SEGLEN / SCHUNK;
    stage_load(0, 0);          CP_COMMIT();
    stage_load(1, SCHUNK);     CP_COMMIT();
    stage_load(2, 2 * SCHUNK); CP_COMMIT();

    for (int ck = 0; ck < nch; ck++) {
        CP_WAIT(2);
        __syncthreads();
        if (ck + 3 < nch) stage_load((ck + 3) & 3, (ck + 3) * SCHUNK);
        CP_COMMIT();

        const char* base = sbuf + (ck & 3) * SSTG2;
        const __half* sd16 = (const __half*)(base);
        const __half* ssg  = (const __half*)(base + 4096);
        const __half* sxi  = (const __half*)(base + 8192);
        const float*  sbc  = (const float*)(base + 12288);
        const int l0 = ck * SCHUNK;

        #pragma unroll 4
        for (int l = 0; l < SCHUNK; l++) {
            float d  = __half2float(sd16[l * 128 + tid]);
            float sg = __half2float(ssg[l * 128 + tid]);
            float xv = __half2float(sxi[l * 128 + tid]);
            const float* Bv = sbc + l * 32;
            const float* Cv = Bv + DSTATE;
            float dx = d * xv;
            float y = 0.f;
            if (pat) {
                float P[DSTATE];
                exp_powers(__expf(d * a1), P);
                #pragma unroll
                for (int s = 0; s < DSTATE; s++) {
                    h[s] = P[s] * h[s] + dx * Bv[s];
                    y = fmaf(h[s], Cv[s], y);
                }
            } else {
                #pragma unroll
                for (int s = 0; s < DSTATE; s++) {
                    h[s] = __expf(d * A[s]) * h[s] + dx * Bv[s];
                    y = fmaf(h[s], Cv[s], y);
                }
            }
            float g = y + xv * Dv;
            gout[(tok0 + l0 + l) * DINNER + c] = __float2half(g * sg);
        }
        __syncthreads();
    }
}

// ---------------------------------------------------------------------------
// Launch
// ---------------------------------------------------------------------------
extern "C" void kernel_launch(void* const* d_in, const int* in_sizes, int n_in,
                              void* d_out, int out_size) {
    const float* x        = (const float*)d_in[0];
    const float* rms_w    = (const float*)d_in[1];
    const float* in_proj  = (const float*)d_in[2];
    const float* conv_w   = (const float*)d_in[3];
    const float* conv_b   = (const float*)d_in[4];
    const float* x_proj   = (const float*)d_in[5];
    const float* dt_w     = (const float*)d_in[6];
    const float* dt_b     = (const float*)d_in[7];
    const float* A_log    = (const float*)d_in[8];
    const float* Dp       = (const float*)d_in[9];
    const float* out_proj = (const float*)d_in[10];
    float* out = (float*)d_out;

    float *dbc, *dbcp, *segsum, *segc;
    __half *xz, *delta, *xn, *xi, *dt, *gg, *ipT, *xpT, *dwT, *opT;
    cudaGetSymbolAddress((void**)&xz,     g_xz);
    cudaGetSymbolAddress((void**)&dbc,    g_dbc);
    cudaGetSymbolAddress((void**)&dbcp,   g_dbcp);
    cudaGetSymbolAddress((void**)&delta,  g_delta);
    cudaGetSymbolAddress((void**)&xn,     g_xn);
    cudaGetSymbolAddress((void**)&xi,     g_xi);
    cudaGetSymbolAddress((void**)&dt,     g_dt);
    cudaGetSymbolAddress((void**)&gg,     g_g);
    cudaGetSymbolAddress((void**)&segsum, g_segsum);
    cudaGetSymbolAddress((void**)&segc,   g_segc);
    cudaGetSymbolAddress((void**)&ipT,    g_ipT);
    cudaGetSymbolAddress((void**)&xpT,    g_xpT);
    cudaGetSymbolAddress((void**)&dwT,    g_dwT);
    cudaGetSymbolAddress((void**)&opT,    g_opT);

    cudaFuncSetAttribute(mma_gemm<1>, cudaFuncAttributeMaxDynamicSharedMemorySize, SMEM_GEMM);
    cudaFuncSetAttribute(mma_gemm<2>, cudaFuncAttributeMaxDynamicSharedMemorySize, SMEM_GEMM);
    cudaFuncSetAttribute(mma_gemm<4>, cudaFuncAttributeMaxDynamicSharedMemorySize, SMEM_GEMM);
    cudaFuncSetAttribute(gemm2_fused, cudaFuncAttributeMaxDynamicSharedMemorySize, SMEM_G2);

    // 0+1. fused prep: 4 weight transposes + rmsnorm in ONE launch
    prep_kernel<<<6464 + NTOK, 256>>>(in_proj, x_proj, dt_w, out_proj,
                                      ipT, xpT, dwT, opT, x, rms_w, xn);

    // 2. xz = xn @ in_proj -> fp16 (z half stored as silu(z))
    {
        dim3 grid(2 * DINNER / 128, NTOK / 128);
        mma_gemm<4><<<grid, 256, SMEM_GEMM>>>(xn, ipT, xz, 2 * DINNER, DIM, DIM,
                                              nullptr);
    }

    // 3+4. conv+silu fused into split-K dbc GEMM (writes xi + partials) + reduce
    {
        dim3 grid(1, NTOK / 128, KSPLIT);
        gemm2_fused<<<grid, 256, SMEM_G2>>>(xz, xpT, conv_w, conv_b, xi, dbcp);
        reduce_dbc<<<NTOK * 128 / 256, 256>>>(dbcp, dbc, dt);
    }

    // 5. delta = softplus(dt @ dt_w + dt_b) -> fp16
    {
        dim3 grid(DINNER / 128, NTOK / 128);
        mma_gemm<1><<<grid, 256, SMEM_GEMM>>>(dt, dwT, delta, DINNER, DTRANK, DTRANK,
                                              dt_b);
    }

    // 6. parallel selective scan (2 passes, 128-thread blocks)
    {
        dim3 g1(BB * (DINNER / 128), NSEG - 1);
        scan_pass1<<<g1, 128>>>(dbc, delta, xi, A_log, segsum, segc);
        dim3 g2(BB * (DINNER / 128), NSEG);
        scan_pass2<<<g2, 128>>>(dbc, delta, xi, xz, A_log, Dp, segsum, segc, gg);
    }

    // 7. out = x + gated @ out_proj
    {
        dim3 grid(DIM / 128, NTOK / 128);
        mma_gemm<2><<<grid, 256, SMEM_GEMM>>>(gg, opT, out, DIM, DINNER, DINNER,
                                              x);
    }
}